// round 17
// baseline (speedup 1.0000x reference)
#include <cuda_runtime.h>
#include <math.h>

#define BATCH 2048
#define TSTEPS 1000
#define NI 40
#define NH 16
#define NR 32
#define NO 2

#define NTILES 32                 // 32-step tiles per batch: 31 full + 1x8
#define OUT_LOSS 0
#define OUT_D2   1
#define OUT_CORR (1 + (size_t)BATCH * TSTEPS * NO)
#define OUT_TOT  (OUT_CORR + 1)

// 262 MB scratch: pre-scaled dendritic currents cur[b][t][r] (x (1-beta_r))
__device__ __align__(16) float g_cur[(size_t)BATCH * TSTEPS * NR];
// 4 MB scratch: packed spike ballots per 4-batch group per step
__device__ __align__(16) uint2 g_ball[(size_t)(BATCH / 4) * TSTEPS];
// staging for the masked/scaled weights, copied into constant memory
__device__ unsigned long long g_wbuf[NR * 20];
// constant-bank weights: c_w[r*20 + j] = packed f32x2 (w[r][2j], w[r][2j+1])
__constant__ __align__(16) unsigned long long c_w[NR * 20];

__device__ __forceinline__ void fma2(unsigned long long& acc,
                                     unsigned long long a,
                                     unsigned long long b) {
    asm("fma.rn.f32x2 %0, %1, %2, %3;" : "=l"(acc) : "l"(a), "l"(b), "l"(acc));
}
__device__ __forceinline__ unsigned long long packf2(float lo, float hi) {
    unsigned long long r;
    asm("mov.b64 %0, {%1, %2};" : "=l"(r) : "f"(lo), "f"(hi));
    return r;
}
__device__ __forceinline__ void unpackf2(unsigned long long v, float& lo, float& hi) {
    asm("mov.b64 {%0, %1}, %2;" : "=f"(lo), "=f"(hi) : "l"(v));
}
__device__ __forceinline__ float sigm(float v) { return 1.0f / (1.0f + expf(-v)); }

// ---- prep: masked, (1-beta)-scaled, packed weights + output scalar init ----
__global__ void prep_kernel(const float* __restrict__ W1,
                            const float* __restrict__ mask,
                            const float* __restrict__ tau_n,
                            float* __restrict__ out) {
    int r = threadIdx.x;  // one lane per row
    if (r == 0) {
        out[OUT_LOSS] = 0.0f;
        int c = 0;
        for (int t = 0; t < TSTEPS; ++t)
            if (t > 10 && ((t - 10) % 15) > 5) c++;
        out[OUT_CORR] = 0.0f;
        out[OUT_TOT] = (float)c * (float)BATCH;
    }
    float om = 1.0f - sigm(tau_n[r]);
    #pragma unroll
    for (int j = 0; j < 20; ++j) {
        int k = 2 * j;
        g_wbuf[r * 20 + j] =
            packf2(W1[r * NI + k]     * mask[r * NI + k]     * om,
                   W1[r * NI + k + 1] * mask[r * NI + k + 1] * om);
    }
}

// ---------------- Kernel A: matvec, one lane per timestep (R11-exact) -------
// warp w: batch b = w/32, tile = w%32 -> steps [32*tile, 32*tile+nsteps).
// Lane s computes cur[b][t0+s][0..31] with weights from the constant bank.
__global__ __launch_bounds__(128) void matvec_kernel(
    const float* __restrict__ x)     // [B, T, NI]
{
    const int wib  = threadIdx.x >> 5;
    const int lane = threadIdx.x & 31;
    const int w    = blockIdx.x * 4 + wib;
    const int b    = w >> 5;
    const int tile = w & 31;
    const int t0   = tile * 32;
    const int nsteps = (tile == 31) ? (TSTEPS - 31 * 32) : 32;   // 8 or 32

    // padded rows: 44 floats (176B) per step -> conflict-free per-lane reads
    __shared__ __align__(16) float sb[4][32 * 44];
    float* sbuf = sb[wib];

    // ---- stage x tile: coalesced GMEM -> transposed smem rows ----
    const float4* xs = reinterpret_cast<const float4*>(
        x + ((size_t)b * TSTEPS + t0) * NI);
    const int nchunk = nsteps * 10;               // 16B chunks in tile
    #pragma unroll
    for (int i = 0; i < 10; ++i) {
        int c = i * 32 + lane;
        if (c < nchunk) {
            float4 v = xs[c];
            int s = c / 10;                        // step row
            int q = c - s * 10;                    // 16B group in row
            *reinterpret_cast<float4*>(&sbuf[s * 44 + q * 4]) = v;
        }
    }
    __syncwarp();

    // ---- per-lane read of own step's 160B (conflict-free LDS.128) ----
    unsigned long long xr[20];
    {
        const ulonglong2* xrow =
            reinterpret_cast<const ulonglong2*>(&sbuf[lane * 44]);
        #pragma unroll
        for (int j2 = 0; j2 < 10; ++j2) {
            ulonglong2 t = xrow[j2];
            xr[2 * j2]     = t.x;
            xr[2 * j2 + 1] = t.y;
        }
    }
    __syncwarp();

    // ---- compute 32 rows; scalar uniform constant loads ----
    #pragma unroll
    for (int rg = 0; rg < 8; ++rg) {
        float4 o;
        #pragma unroll
        for (int rr = 0; rr < 4; ++rr) {
            const int r = rg * 4 + rr;
            unsigned long long acc0 = 0ull, acc1 = 0ull;
            #pragma unroll
            for (int j = 0; j < 10; ++j) {
                fma2(acc0, c_w[r * 20 + j],      xr[j]);
                fma2(acc1, c_w[r * 20 + 10 + j], xr[10 + j]);
            }
            float s0, s1, s2, s3;
            unpackf2(acc0, s0, s1);
            unpackf2(acc1, s2, s3);
            reinterpret_cast<float*>(&o)[rr] = (s0 + s1) + (s2 + s3);
        }
        if (lane < nsteps)
            *reinterpret_cast<float4*>(&sbuf[lane * 44 + rg * 4]) = o;
    }
    __syncwarp();

    // ---- store tile: transposed smem -> coalesced GMEM ----
    float4* cp = reinterpret_cast<float4*>(
        g_cur + ((size_t)b * TSTEPS + t0) * NR);
    const int ochunk = nsteps * 8;                // 16B chunks out
    #pragma unroll
    for (int i = 0; i < 8; ++i) {
        int c = i * 32 + lane;
        if (c < ochunk) {
            int s = c >> 3;
            int q = c & 7;
            cp[c] = *reinterpret_cast<float4*>(&sbuf[s * 44 + q * 4]);
        }
    }
}

// ---------------- Kernel B: pure state recurrence (R11-exact) ---------------
// lane gl (0..7) of each 8-lane group owns rows 4gl..4gl+3 = neurons 2gl,2gl+1
#define PD 20

__global__ __launch_bounds__(128) void recur_kernel(
    const float* __restrict__ tau_m,  // [NH]
    const float* __restrict__ tau_n)  // [NR]
{
    const int lane = threadIdx.x & 31;
    const int warp = (blockIdx.x * 128 + threadIdx.x) >> 5;
    const int g    = lane >> 3;
    const int gl   = lane & 7;
    const int b    = warp * 4 + g;
    const unsigned FULL = 0xffffffffu;

    const float4 tn4 = *reinterpret_cast<const float4*>(tau_n + gl * 4);
    const float be0 = sigm(tn4.x), be1 = sigm(tn4.y);
    const float be2 = sigm(tn4.z), be3 = sigm(tn4.w);
    const float2 tm2 = *reinterpret_cast<const float2*>(tau_m + gl * 2);
    const float alA = sigm(tm2.x), omA = 1.0f - alA;
    const float alB = sigm(tm2.y), omB = 1.0f - alB;

    const float4* cp = reinterpret_cast<const float4*>(g_cur)
                     + (size_t)b * TSTEPS * (NR / 4) + gl;
    uint2* bp = g_ball + (size_t)warp * TSTEPS;

    float4 pc[PD];
    #pragma unroll
    for (int j = 0; j < PD; ++j) pc[j] = cp[(size_t)j * (NR / 4)];

    float d0 = 0.f, d1 = 0.f, d2 = 0.f, d3 = 0.f;
    float memA = 0.f, memB = 0.f, spkA = 0.f, spkB = 0.f;

    for (int tt = 0; tt < TSTEPS; tt += PD) {
        #pragma unroll
        for (int u = 0; u < PD; ++u) {
            const int t = tt + u;
            float4 v = pc[u];
            const int tn_ = t + PD;
            if (tn_ < TSTEPS) pc[u] = cp[(size_t)tn_ * (NR / 4)];

            d0 = fmaf(be0, d0, v.x);
            d1 = fmaf(be1, d1, v.y);
            d2 = fmaf(be2, d2, v.z);
            d3 = fmaf(be3, d3, v.w);
            float lA = d0 + d1;
            float lB = d2 + d3;

            memA = fmaf(alA, memA - spkA, omA * lA);
            memB = fmaf(alB, memB - spkB, omB * lB);
            bool sA = memA > 1.0f;               // VTH = 1
            bool sB = memB > 1.0f;
            spkA = sA ? 1.0f : 0.0f;
            spkB = sB ? 1.0f : 0.0f;

            unsigned bA = __ballot_sync(FULL, sA);
            unsigned bB = __ballot_sync(FULL, sB);
            if (lane == 0) bp[t] = make_uint2(bA, bB);
        }
    }
}

// ---------------- Kernel C: logits + CE, 2 batch rows per block -------------
// stride-256 t-loop: 256 % 15 == 1 -> phase advances by exactly 1 per iter,
// so the per-element (t-10)%15 collapses to an increment + compare.
#define CBLK 256

__global__ __launch_bounds__(CBLK) void logits_kernel(
    const int*   __restrict__ target, // [B, T]
    const float* __restrict__ W2,     // [NO, NH]
    const float* __restrict__ b2,     // [NO]
    float*       __restrict__ out)
{
    __shared__ float LA0[256], LA1[256], LB0[256], LB1[256];
    __shared__ float redL[CBLK / 32], redC[CBLK / 32];

    {
        int m = threadIdx.x;
        if (m < 256) {
            float a0 = 0.f, a1 = 0.f, c0 = 0.f, c1 = 0.f;
            #pragma unroll
            for (int gl = 0; gl < 8; ++gl) {
                if ((m >> gl) & 1) {
                    a0 += W2[2 * gl];
                    a1 += W2[NH + 2 * gl];
                    c0 += W2[2 * gl + 1];
                    c1 += W2[NH + 2 * gl + 1];
                }
            }
            LA0[m] = a0; LA1[m] = a1; LB0[m] = c0; LB1[m] = c1;
        }
    }
    __syncthreads();

    const float b20 = b2[0], b21 = b2[1];
    // initial phase for t = threadIdx.x: (t - 10) mod 15, non-negative
    const int ph0 = (threadIdx.x + 5) % 15;       // == (t-10) mod 15 for t=tid

    float lossAcc = 0.0f;
    int   corrAcc = 0;

    #pragma unroll
    for (int rb = 0; rb < 2; ++rb) {
        const int b  = blockIdx.x * 2 + rb;
        const int sh = (b & 3) * 8;
        const uint2* ballRow = g_ball + (size_t)(b >> 2) * TSTEPS;
        const int*   tgtRow  = target + (size_t)b * TSTEPS;
        float*       d2Row   = out + OUT_D2 + (size_t)b * TSTEPS * 2;

        int ph = ph0;
        for (int t = threadIdx.x; t < TSTEPS; t += CBLK) {
            uint2 ball = ballRow[t];              // coalesced within block
            int a = (ball.x >> sh) & 255;
            int c = (ball.y >> sh) & 255;
            float l0 = b20 + LA0[a] + LB0[c];
            float l1 = b21 + LA1[a] + LB1[c];
            d2Row[2 * t]     = l0;
            d2Row[2 * t + 1] = l1;

            bool flag = (ph > 5) && (t > 10);
            ph = (ph == 14) ? 0 : ph + 1;         // stride 256 == +1 mod 15
            if (flag) {
                int tgt = tgtRow[t];
                float z  = l1 - l0;
                float p1 = 1.0f / (1.0f + __expf(-z));
                float p0 = 1.0f - p1;
                float lse = __logf(__expf(p0) + __expf(p1)); // double-softmax CE
                float ptgt = tgt ? p1 : p0;
                lossAcc += (lse - ptgt);
                corrAcc += (((z > 0.0f) ? 1 : 0) == tgt);
            }
        }
    }

    const unsigned FULL = 0xffffffffu;
    float corrF = (float)corrAcc;
    #pragma unroll
    for (int o = 16; o > 0; o >>= 1) {
        lossAcc += __shfl_xor_sync(FULL, lossAcc, o);
        corrF   += __shfl_xor_sync(FULL, corrF, o);
    }
    int wid = threadIdx.x >> 5;
    if ((threadIdx.x & 31) == 0) { redL[wid] = lossAcc; redC[wid] = corrF; }
    __syncthreads();
    if (threadIdx.x == 0) {
        float L = 0.f, C = 0.f;
        #pragma unroll
        for (int k = 0; k < CBLK / 32; ++k) { L += redL[k]; C += redC[k]; }
        atomicAdd(&out[OUT_LOSS], L * (1.0f / (float)BATCH));
        atomicAdd(&out[OUT_CORR], C);
    }
}

extern "C" void kernel_launch(void* const* d_in, const int* in_sizes, int n_in,
                              void* d_out, int out_size) {
    const float* x      = (const float*)d_in[0];
    const int*   target = (const int*)  d_in[1];
    const float* W1     = (const float*)d_in[2];
    const float* tau_m  = (const float*)d_in[3];
    const float* tau_n  = (const float*)d_in[4];
    const float* mask   = (const float*)d_in[5];
    const float* W2     = (const float*)d_in[6];
    const float* b2     = (const float*)d_in[7];
    float* out = (float*)d_out;

    prep_kernel<<<1, 32>>>(W1, mask, tau_n, out);

    // device-to-device async copy of the packed weights into constant memory
    void* wsrc = nullptr;
    cudaGetSymbolAddress(&wsrc, g_wbuf);
    cudaMemcpyToSymbolAsync(c_w, wsrc, sizeof(unsigned long long) * NR * 20,
                            0, cudaMemcpyDeviceToDevice, 0);

    matvec_kernel<<<(BATCH * NTILES) / 4, 128>>>(x);
    recur_kernel<<<(BATCH / 4) * 32 / 128, 128>>>(tau_m, tau_n);
    logits_kernel<<<BATCH / 2, CBLK>>>(target, W2, b2, out);
}